// round 5
// baseline (speedup 1.0000x reference)
#include <cuda_runtime.h>
#include <cuda_bf16.h>
#include <math.h>
#include <stdint.h>

#define N_NODES 30000
#define E_RAW   480000
#define E_TOT   (E_RAW + N_NODES)
#define MAXH    4
#define MAXHC   512
#define TPB     256
#define MAXK    512

// ---------------- scratch ----------------------------------------------------
__device__ float g_h[N_NODES * MAXHC];
__device__ float g_act[N_NODES * MAXHC];
__device__ float g_asrc[N_NODES * MAXH];
__device__ float g_adst[N_NODES * MAXH];
__device__ float g_alpha[E_TOT * MAXH];
__device__ int   g_src[E_TOT];
__device__ int   g_dst[E_TOT];
__device__ int   g_csr_src[E_TOT];
__device__ int   g_deg[N_NODES];
__device__ int   g_rowptr[N_NODES + 1];
__device__ int   g_cursor[N_NODES];
__device__ int   g_is64;
__device__ __align__(16) __nv_bfloat16 g_Ahi[N_NODES * MAXK];
__device__ __align__(16) __nv_bfloat16 g_Alo[N_NODES * MAXK];
__device__ __align__(16) __nv_bfloat16 g_Whi[MAXK * MAXHC];   // [N,K] transposed
__device__ __align__(16) __nv_bfloat16 g_Wlo[MAXK * MAXHC];
#define SB 128
#define NSB ((N_NODES + SB - 1) / SB)
__device__ int g_bsum[NSB];

// ---------------- helpers -----------------------------------------------------
__device__ __forceinline__ uint32_t smem_u32(const void* p) {
    uint32_t a;
    asm("{ .reg .u64 t; cvta.to.shared.u64 t, %1; cvt.u32.u64 %0, t; }" : "=r"(a) : "l"(p));
    return a;
}
__device__ __forceinline__ uint32_t sw128(uint32_t off) { return off ^ ((off >> 3) & 0x70); }
__device__ __forceinline__ int clampN(int v) {
    return v < 0 ? 0 : (v >= N_NODES ? N_NODES - 1 : v);
}
#define LDSM_X4(r0, r1, r2, r3, addr) \
    asm volatile("ldmatrix.sync.aligned.m8n8.x4.shared.b16 {%0,%1,%2,%3}, [%4];" \
                 : "=r"(r0), "=r"(r1), "=r"(r2), "=r"(r3) : "r"(addr))
__device__ __forceinline__ void mma16816(float* c, const uint32_t* a, const uint32_t* b) {
    asm volatile(
        "mma.sync.aligned.m16n8k16.row.col.f32.bf16.bf16.f32 "
        "{%0,%1,%2,%3}, {%4,%5,%6,%7}, {%8,%9}, {%0,%1,%2,%3};"
        : "+f"(c[0]), "+f"(c[1]), "+f"(c[2]), "+f"(c[3])
        : "r"(a[0]), "r"(a[1]), "r"(a[2]), "r"(a[3]), "r"(b[0]), "r"(b[1]));
}

// ---------------- preprocessing ----------------------------------------------
__global__ void detect_dtype_kernel(const int* __restrict__ ei32) {
    int all_odd_zero = 1;
    for (int i = 0; i < 32; i++)
        if (ei32[2 * i + 1] != 0) { all_odd_zero = 0; break; }
    g_is64 = all_odd_zero;
}
__global__ void zero_deg_kernel() {
    int i = blockIdx.x * blockDim.x + threadIdx.x;
    if (i < N_NODES) g_deg[i] = 0;
}
__global__ void build_edges_kernel(const void* __restrict__ ei_raw) {
    int i = blockIdx.x * blockDim.x + threadIdx.x;
    if (i >= E_TOT) return;
    int s, d;
    if (i < E_RAW) {
        if (g_is64) {
            const long long* e = (const long long*)ei_raw;
            s = (int)e[i]; d = (int)e[E_RAW + i];
        } else {
            const int* e = (const int*)ei_raw;
            s = e[i]; d = e[E_RAW + i];
        }
        s = clampN(s); d = clampN(d);
    } else {
        s = i - E_RAW; d = s;
    }
    g_src[i] = s; g_dst[i] = d;
    atomicAdd(&g_deg[d], 1);
}
__global__ void scan1_kernel() {
    __shared__ int sm[SB];
    int i = blockIdx.x * SB + threadIdx.x;
    sm[threadIdx.x] = (i < N_NODES) ? g_deg[i] : 0;
    __syncthreads();
    for (int off = SB / 2; off > 0; off >>= 1) {
        if (threadIdx.x < off) sm[threadIdx.x] += sm[threadIdx.x + off];
        __syncthreads();
    }
    if (threadIdx.x == 0) g_bsum[blockIdx.x] = sm[0];
}
__global__ void scan2_kernel() {
    __shared__ int sm[256];
    int t = threadIdx.x;
    int v = (t < NSB) ? g_bsum[t] : 0;
    sm[t] = v;
    __syncthreads();
    for (int off = 1; off < 256; off <<= 1) {
        int u = (t >= off) ? sm[t - off] : 0;
        __syncthreads();
        sm[t] += u;
        __syncthreads();
    }
    if (t < NSB) g_bsum[t] = sm[t] - v;
}
__global__ void scan3_kernel() {
    __shared__ int sm[SB];
    int t = threadIdx.x;
    int i = blockIdx.x * SB + t;
    int d = (i < N_NODES) ? g_deg[i] : 0;
    sm[t] = d;
    __syncthreads();
    for (int off = 1; off < SB; off <<= 1) {
        int u = (t >= off) ? sm[t - off] : 0;
        __syncthreads();
        sm[t] += u;
        __syncthreads();
    }
    int excl = g_bsum[blockIdx.x] + sm[t] - d;
    if (i < N_NODES) { g_rowptr[i] = excl; g_cursor[i] = excl; }
    if (blockIdx.x == 0 && t == 0) g_rowptr[N_NODES] = E_TOT;
}
__global__ void scatter_kernel() {
    int e = blockIdx.x * blockDim.x + threadIdx.x;
    if (e >= E_TOT) return;
    int d = g_dst[e];
    int pos = atomicAdd(&g_cursor[d], 1);
    g_csr_src[pos] = g_src[e];
}

// ---------------- fp32 -> bf16 hi/lo splits ----------------------------------
__global__ void split_kernel(const float* __restrict__ src, int total4) {
    int i = blockIdx.x * blockDim.x + threadIdx.x;
    if (i >= total4) return;
    float4 v = ((const float4*)src)[i];
    __nv_bfloat16 h0 = __float2bfloat16(v.x), h1 = __float2bfloat16(v.y);
    __nv_bfloat16 h2 = __float2bfloat16(v.z), h3 = __float2bfloat16(v.w);
    __nv_bfloat16 l0 = __float2bfloat16(v.x - __bfloat162float(h0));
    __nv_bfloat16 l1 = __float2bfloat16(v.y - __bfloat162float(h1));
    __nv_bfloat16 l2 = __float2bfloat16(v.z - __bfloat162float(h2));
    __nv_bfloat16 l3 = __float2bfloat16(v.w - __bfloat162float(h3));
    ((__nv_bfloat162*)g_Ahi)[2 * i + 0] = __nv_bfloat162(h0, h1);
    ((__nv_bfloat162*)g_Ahi)[2 * i + 1] = __nv_bfloat162(h2, h3);
    ((__nv_bfloat162*)g_Alo)[2 * i + 0] = __nv_bfloat162(l0, l1);
    ((__nv_bfloat162*)g_Alo)[2 * i + 1] = __nv_bfloat162(l2, l3);
}
// transpose W[K,N] -> Whi/Wlo [N,K]
__global__ void wsplit_kernel(const float* __restrict__ W, int K, int N) {
    int idx = blockIdx.x * blockDim.x + threadIdx.x;
    if (idx >= K * N) return;
    int n = idx / K, k = idx - n * K;
    float v = W[(size_t)k * N + n];
    __nv_bfloat16 h = __float2bfloat16(v);
    g_Whi[idx] = h;
    g_Wlo[idx] = __float2bfloat16(v - __bfloat162float(h));
}

// ---------------- HMMA bf16 GEMM (3-pass split) -------------------------------
// D[M,N] = Ahi@Whi^T + Ahi@Wlo^T + Alo@Whi^T; A [M,K] K-major, W^T [N,K] K-major.
// Block tile 128 x BN, BK=64 chunks, double-buffered, 8 warps (2 x 4).
template <int BN>
__global__ __launch_bounds__(256, 1) void mma_gemm_kernel(float* __restrict__ D,
                                                          int M, int N, int K) {
    extern __shared__ __align__(1024) char smem[];
    char* Abuf[2] = { smem, smem + 16384 };
    char* Bbuf[2] = { smem + 32768, smem + 32768 + BN * 128 };

    const int tid = threadIdx.x;
    const int wid = tid >> 5, lane = tid & 31;
    const int rowBase = blockIdx.y * 128;
    const int colBase = blockIdx.x * BN;
    const int wr = wid >> 2, wc = wid & 3;      // warp grid 2 x 4
    constexpr int WN = BN / 4;                  // warp n width (32 or 16)
    constexpr int NT = WN / 8;                  // n8 tiles per warp (4 or 2)
    const int warpRow = wr * 64, warpCol = wc * WN;

    float acc[4][NT][4];
#pragma unroll
    for (int i = 0; i < 4; i++)
#pragma unroll
        for (int j = 0; j < NT; j++)
#pragma unroll
            for (int q = 0; q < 4; q++) acc[i][j][q] = 0.f;

    const int kch = K / 64;
    const int NCH = 3 * kch;

    auto load_chunk = [&](int i, char* sA, char* sB) {
        int pass = i / kch, kc = i - pass * kch;
        const __nv_bfloat16* Asrc = (pass == 2) ? g_Alo : g_Ahi;
        const __nv_bfloat16* Bsrc = (pass == 1) ? g_Wlo : g_Whi;
#pragma unroll
        for (int j = 0; j < 4; j++) {                 // A: 128 rows x 8 x 16B
            int q = tid + j * 256;
            int r = q >> 3, c16 = q & 7;
            uint4 v = make_uint4(0, 0, 0, 0);
            if (rowBase + r < M)
                v = *(const uint4*)(Asrc + (size_t)(rowBase + r) * K + kc * 64 + c16 * 8);
            *(uint4*)(sA + sw128(r * 128 + c16 * 16)) = v;
        }
#pragma unroll
        for (int j = 0; j < BN / 32; j++) {           // B: BN rows x 8 x 16B
            int q = tid + j * 256;
            int r = q >> 3, c16 = q & 7;
            uint4 v = *(const uint4*)(Bsrc + (size_t)(colBase + r) * K + kc * 64 + c16 * 8);
            *(uint4*)(sB + sw128(r * 128 + c16 * 16)) = v;
        }
    };

    load_chunk(0, Abuf[0], Bbuf[0]);
    __syncthreads();

    const int g = lane >> 3;            // ldmatrix address group
    const int l7 = lane & 7;

    for (int i = 0; i < NCH; i++) {
        int cur = i & 1;
        if (i + 1 < NCH) load_chunk(i + 1, Abuf[cur ^ 1], Bbuf[cur ^ 1]);

        uint32_t aBase = smem_u32(Abuf[cur]);
        uint32_t bBase = smem_u32(Bbuf[cur]);
#pragma unroll
        for (int kk = 0; kk < 4; kk++) {
            uint32_t af[4][4];
#pragma unroll
            for (int mt = 0; mt < 4; mt++) {
                int row = warpRow + mt * 16 + l7 + ((g & 1) ? 8 : 0);
                int kb = (kk * 16 + ((g >= 2) ? 8 : 0)) * 2;
                uint32_t addr = aBase + sw128((uint32_t)(row * 128 + kb));
                LDSM_X4(af[mt][0], af[mt][1], af[mt][2], af[mt][3], addr);
            }
            uint32_t bf[NT][2];
#pragma unroll
            for (int np = 0; np < NT / 2; np++) {      // x4 loads 2 n8 tiles
                int row = warpCol + np * 16 + l7 + ((g >= 2) ? 8 : 0);
                int kb = (kk * 16 + ((g & 1) ? 8 : 0)) * 2;
                uint32_t addr = bBase + sw128((uint32_t)(row * 128 + kb));
                uint32_t r0, r1, r2, r3;
                LDSM_X4(r0, r1, r2, r3, addr);
                bf[np * 2][0] = r0;  bf[np * 2][1] = r1;
                bf[np * 2 + 1][0] = r2; bf[np * 2 + 1][1] = r3;
            }
#pragma unroll
            for (int mt = 0; mt < 4; mt++)
#pragma unroll
                for (int nt = 0; nt < NT; nt++)
                    mma16816(acc[mt][nt], af[mt], bf[nt]);
        }
        __syncthreads();
    }

    // epilogue
    const int qr = lane >> 2, qc = lane & 3;
#pragma unroll
    for (int mt = 0; mt < 4; mt++) {
        int r0 = rowBase + warpRow + mt * 16 + qr;
#pragma unroll
        for (int nt = 0; nt < NT; nt++) {
            int col = colBase + warpCol + nt * 8 + qc * 2;
            if (r0 < M)
                *(float2*)&D[(size_t)r0 * N + col] = make_float2(acc[mt][nt][0], acc[mt][nt][1]);
            if (r0 + 8 < M)
                *(float2*)&D[(size_t)(r0 + 8) * N + col] = make_float2(acc[mt][nt][2], acc[mt][nt][3]);
        }
    }
}

// ---------------- per-(node,head) attention logits ---------------------------
__global__ void node_alpha_kernel(const float* __restrict__ a_s,
                                  const float* __restrict__ a_d,
                                  int H, int C) {
    int warp = (blockIdx.x * blockDim.x + threadIdx.x) >> 5;
    int lane = threadIdx.x & 31;
    if (warp >= N_NODES * H) return;
    int n = warp / H, hh = warp - n * H;
    const float* hv = g_h + (size_t)n * H * C + hh * C;
    float ss = 0.f, sd = 0.f;
    for (int c = lane; c < C; c += 32) {
        float v = hv[c];
        ss += v * a_s[hh * C + c];
        sd += v * a_d[hh * C + c];
    }
#pragma unroll
    for (int o = 16; o; o >>= 1) {
        ss += __shfl_down_sync(0xffffffffu, ss, o);
        sd += __shfl_down_sync(0xffffffffu, sd, o);
    }
    if (lane == 0) { g_asrc[warp] = ss; g_adst[warp] = sd; }
}

// ---------------- per-dst softmax --------------------------------------------
template <int H>
__global__ void attn_alpha_kernel() {
    int d = blockIdx.x;
    int tid = threadIdx.x;
    int lane = tid & 31, wid = tid >> 5;
    int start = g_rowptr[d], end = g_rowptr[d + 1];
    int deg = end - start;

    __shared__ float red[H][4];
    __shared__ float bmax[H], bsum[H];

    float adst[H];
#pragma unroll
    for (int h = 0; h < H; h++) adst[h] = g_adst[d * H + h];

    float lmax[H];
#pragma unroll
    for (int h = 0; h < H; h++) lmax[h] = -INFINITY;
    for (int i = tid; i < deg; i += 128) {
        int s = g_csr_src[start + i];
#pragma unroll
        for (int h = 0; h < H; h++) {
            float v = g_asrc[s * H + h] + adst[h];
            v = (v > 0.f) ? v : 0.2f * v;
            lmax[h] = fmaxf(lmax[h], v);
        }
    }
#pragma unroll
    for (int h = 0; h < H; h++) {
#pragma unroll
        for (int o = 16; o; o >>= 1) lmax[h] = fmaxf(lmax[h], __shfl_down_sync(0xffffffffu, lmax[h], o));
        if (lane == 0) red[h][wid] = lmax[h];
    }
    __syncthreads();
    if (tid < H)
        bmax[tid] = fmaxf(fmaxf(red[tid][0], red[tid][1]), fmaxf(red[tid][2], red[tid][3]));
    __syncthreads();

    float lsum[H];
#pragma unroll
    for (int h = 0; h < H; h++) lsum[h] = 0.f;
    for (int i = tid; i < deg; i += 128) {
        int s = g_csr_src[start + i];
#pragma unroll
        for (int h = 0; h < H; h++) {
            float v = g_asrc[s * H + h] + adst[h];
            v = (v > 0.f) ? v : 0.2f * v;
            lsum[h] += __expf(v - bmax[h]);
        }
    }
#pragma unroll
    for (int h = 0; h < H; h++) {
#pragma unroll
        for (int o = 16; o; o >>= 1) lsum[h] += __shfl_down_sync(0xffffffffu, lsum[h], o);
        if (lane == 0) red[h][wid] = lsum[h];
    }
    __syncthreads();
    if (tid < H) bsum[tid] = 1.f / (red[tid][0] + red[tid][1] + red[tid][2] + red[tid][3]);
    __syncthreads();

    for (int i = tid; i < deg; i += 128) {
        int s = g_csr_src[start + i];
#pragma unroll
        for (int h = 0; h < H; h++) {
            float v = g_asrc[s * H + h] + adst[h];
            v = (v > 0.f) ? v : 0.2f * v;
            g_alpha[(size_t)(start + i) * H + h] = __expf(v - bmax[h]) * bsum[h];
        }
    }
}

// ---------------- gather-aggregate + bias + relu ------------------------------
template <int H, int C>
__global__ void agg_kernel(const float* __restrict__ bias, float* __restrict__ out) {
    constexpr int HC = H * C;
    constexpr int NV = HC / 4;
    int d = blockIdx.x;
    int tid = threadIdx.x;
    if (tid >= NV) return;
    int c4 = tid * 4;
    int head = c4 / C;
    int start = g_rowptr[d], end = g_rowptr[d + 1];

    float4 acc = make_float4(0.f, 0.f, 0.f, 0.f);
    for (int pos = start; pos < end; pos++) {
        int s = g_csr_src[pos];
        float al = g_alpha[(size_t)pos * H + head];
        float4 hv = *(const float4*)&g_h[(size_t)s * HC + c4];
        acc.x += hv.x * al; acc.y += hv.y * al;
        acc.z += hv.z * al; acc.w += hv.w * al;
    }
    float4 bv = *(const float4*)&bias[c4];
    acc.x = fmaxf(acc.x + bv.x, 0.f);
    acc.y = fmaxf(acc.y + bv.y, 0.f);
    acc.z = fmaxf(acc.z + bv.z, 0.f);
    acc.w = fmaxf(acc.w + bv.w, 0.f);
    *(float4*)&out[(size_t)d * HC + c4] = acc;
}

// ---------------- driver ------------------------------------------------------
extern "C" void kernel_launch(void* const* d_in, const int* in_sizes, int n_in,
                              void* d_out, int out_size) {
    const float* x  = (const float*)d_in[0];
    const void*  ei = d_in[1];
    float* out = (float*)d_out;

    void* p;
    cudaGetSymbolAddress(&p, g_act);
    float* act_ptr = (float*)p;
    cudaGetSymbolAddress(&p, g_h);
    float* h_ptr = (float*)p;

    static bool attr_done = false;
    if (!attr_done) {
        cudaFuncSetAttribute(mma_gemm_kernel<128>, cudaFuncAttributeMaxDynamicSharedMemorySize,
                             2 * 16384 + 2 * 128 * 128);
        cudaFuncSetAttribute(mma_gemm_kernel<64>, cudaFuncAttributeMaxDynamicSharedMemorySize,
                             2 * 16384 + 2 * 64 * 128);
        attr_done = true;
    }

    struct Cfg { const float *W, *as, *ad, *b; int Fin, H, C; };
    Cfg cfg[4] = {
        { (const float*)d_in[2],  (const float*)d_in[3],  (const float*)d_in[4],  (const float*)d_in[5],  256, 4, 128 },
        { (const float*)d_in[6],  (const float*)d_in[7],  (const float*)d_in[8],  (const float*)d_in[9],  512, 4, 128 },
        { (const float*)d_in[10], (const float*)d_in[11], (const float*)d_in[12], (const float*)d_in[13], 512, 4,  64 },
        { (const float*)d_in[14], (const float*)d_in[15], (const float*)d_in[16], (const float*)d_in[17], 256, 1,  64 },
    };

    detect_dtype_kernel<<<1, 1>>>((const int*)ei);
    zero_deg_kernel<<<(N_NODES + TPB - 1) / TPB, TPB>>>();
    build_edges_kernel<<<(E_TOT + TPB - 1) / TPB, TPB>>>(ei);
    scan1_kernel<<<NSB, SB>>>();
    scan2_kernel<<<1, 256>>>();
    scan3_kernel<<<NSB, SB>>>();
    scatter_kernel<<<(E_TOT + TPB - 1) / TPB, TPB>>>();

    const int MT = (N_NODES + 127) / 128;      // 235 M-tiles

    for (int L = 0; L < 4; L++) {
        const Cfg& c = cfg[L];
        int HC = c.H * c.C;
        const float* A = (L == 0) ? x : act_ptr;

        int total4 = N_NODES * c.Fin / 4;
        split_kernel<<<(total4 + TPB - 1) / TPB, TPB>>>(A, total4);
        wsplit_kernel<<<(c.Fin * HC + TPB - 1) / TPB, TPB>>>(c.W, c.Fin, HC);

        if (HC >= 128) {
            dim3 grid(HC / 128, MT);
            mma_gemm_kernel<128><<<grid, 256, 2 * 16384 + 2 * 128 * 128>>>(h_ptr, N_NODES, HC, c.Fin);
        } else {
            dim3 grid(HC / 64, MT);
            mma_gemm_kernel<64><<<grid, 256, 2 * 16384 + 2 * 64 * 128>>>(h_ptr, N_NODES, HC, c.Fin);
        }

        int nwarps = N_NODES * c.H;
        node_alpha_kernel<<<(nwarps * 32 + TPB - 1) / TPB, TPB>>>(c.as, c.ad, c.H, c.C);

        float* dst = (L == 3) ? out : act_ptr;
        switch (L) {
            case 0:
                attn_alpha_kernel<4><<<N_NODES, 128>>>();
                agg_kernel<4, 128><<<N_NODES, 128>>>(c.b, dst);
                break;
            case 1:
                attn_alpha_kernel<4><<<N_NODES, 128>>>();
                agg_kernel<4, 128><<<N_NODES, 128>>>(c.b, dst);
                break;
            case 2:
                attn_alpha_kernel<4><<<N_NODES, 128>>>();
                agg_kernel<4, 64><<<N_NODES, 64>>>(c.b, dst);
                break;
            case 3:
                attn_alpha_kernel<1><<<N_NODES, 128>>>();
                agg_kernel<1, 64><<<N_NODES, 32>>>(c.b, dst);
                break;
        }
    }
}

// round 6
// speedup vs baseline: 1.7814x; 1.7814x over previous
#include <cuda_runtime.h>
#include <cuda_bf16.h>
#include <math.h>
#include <stdint.h>

#define N_NODES 30000
#define E_RAW   480000
#define E_TOT   (E_RAW + N_NODES)
#define MAXH    4
#define MAXHC   512
#define TPB     256
#define MAXK    512

// ---------------- scratch ----------------------------------------------------
__device__ float g_h[N_NODES * MAXHC];
__device__ float g_asrc[N_NODES * MAXH];
__device__ float g_adst[N_NODES * MAXH];
__device__ float g_alpha[E_TOT * MAXH];
__device__ int   g_src[E_TOT];
__device__ int   g_dst[E_TOT];
__device__ int   g_csr_src[E_TOT];
__device__ int   g_deg[N_NODES];
__device__ int   g_rowptr[N_NODES + 1];
__device__ int   g_cursor[N_NODES];
__device__ int   g_is64;
__device__ __align__(16) __nv_bfloat16 g_Ahi[N_NODES * MAXK];
__device__ __align__(16) __nv_bfloat16 g_Alo[N_NODES * MAXK];
__device__ __align__(16) __nv_bfloat16 g_Whi[MAXK * MAXHC];   // [N,K] transposed
__device__ __align__(16) __nv_bfloat16 g_Wlo[MAXK * MAXHC];
#define SB 128
#define NSB ((N_NODES + SB - 1) / SB)
__device__ int g_bsum[NSB];

// ---------------- helpers -----------------------------------------------------
__device__ __forceinline__ uint32_t smem_u32(const void* p) {
    uint32_t a;
    asm("{ .reg .u64 t; cvta.to.shared.u64 t, %1; cvt.u32.u64 %0, t; }" : "=r"(a) : "l"(p));
    return a;
}
__device__ __forceinline__ uint32_t sw128(uint32_t off) { return off ^ ((off >> 3) & 0x70); }
__device__ __forceinline__ int clampN(int v) {
    return v < 0 ? 0 : (v >= N_NODES ? N_NODES - 1 : v);
}
#define LDSM_X4(r0, r1, r2, r3, addr) \
    asm volatile("ldmatrix.sync.aligned.m8n8.x4.shared.b16 {%0,%1,%2,%3}, [%4];" \
                 : "=r"(r0), "=r"(r1), "=r"(r2), "=r"(r3) : "r"(addr))
#define CP_ASYNC16(saddr, gptr, bytes) \
    asm volatile("cp.async.cg.shared.global [%0], [%1], 16, %2;" \
                 :: "r"(saddr), "l"(gptr), "r"(bytes))
#define CP_COMMIT()  asm volatile("cp.async.commit_group;" ::: "memory")
#define CP_WAIT0()   asm volatile("cp.async.wait_group 0;" ::: "memory")
__device__ __forceinline__ void mma16816(float* c, const uint32_t* a, const uint32_t* b) {
    asm volatile(
        "mma.sync.aligned.m16n8k16.row.col.f32.bf16.bf16.f32 "
        "{%0,%1,%2,%3}, {%4,%5,%6,%7}, {%8,%9}, {%0,%1,%2,%3};"
        : "+f"(c[0]), "+f"(c[1]), "+f"(c[2]), "+f"(c[3])
        : "r"(a[0]), "r"(a[1]), "r"(a[2]), "r"(a[3]), "r"(b[0]), "r"(b[1]));
}

// ---------------- preprocessing ----------------------------------------------
__global__ void detect_dtype_kernel(const int* __restrict__ ei32) {
    int all_odd_zero = 1;
    for (int i = 0; i < 32; i++)
        if (ei32[2 * i + 1] != 0) { all_odd_zero = 0; break; }
    g_is64 = all_odd_zero;
}
__global__ void zero_deg_kernel() {
    int i = blockIdx.x * blockDim.x + threadIdx.x;
    if (i < N_NODES) g_deg[i] = 0;
}
__global__ void build_edges_kernel(const void* __restrict__ ei_raw) {
    int i = blockIdx.x * blockDim.x + threadIdx.x;
    if (i >= E_TOT) return;
    int s, d;
    if (i < E_RAW) {
        if (g_is64) {
            const long long* e = (const long long*)ei_raw;
            s = (int)e[i]; d = (int)e[E_RAW + i];
        } else {
            const int* e = (const int*)ei_raw;
            s = e[i]; d = e[E_RAW + i];
        }
        s = clampN(s); d = clampN(d);
    } else {
        s = i - E_RAW; d = s;
    }
    g_src[i] = s; g_dst[i] = d;
    atomicAdd(&g_deg[d], 1);
}
__global__ void scan1_kernel() {
    __shared__ int sm[SB];
    int i = blockIdx.x * SB + threadIdx.x;
    sm[threadIdx.x] = (i < N_NODES) ? g_deg[i] : 0;
    __syncthreads();
    for (int off = SB / 2; off > 0; off >>= 1) {
        if (threadIdx.x < off) sm[threadIdx.x] += sm[threadIdx.x + off];
        __syncthreads();
    }
    if (threadIdx.x == 0) g_bsum[blockIdx.x] = sm[0];
}
__global__ void scan2_kernel() {
    __shared__ int sm[256];
    int t = threadIdx.x;
    int v = (t < NSB) ? g_bsum[t] : 0;
    sm[t] = v;
    __syncthreads();
    for (int off = 1; off < 256; off <<= 1) {
        int u = (t >= off) ? sm[t - off] : 0;
        __syncthreads();
        sm[t] += u;
        __syncthreads();
    }
    if (t < NSB) g_bsum[t] = sm[t] - v;
}
__global__ void scan3_kernel() {
    __shared__ int sm[SB];
    int t = threadIdx.x;
    int i = blockIdx.x * SB + t;
    int d = (i < N_NODES) ? g_deg[i] : 0;
    sm[t] = d;
    __syncthreads();
    for (int off = 1; off < SB; off <<= 1) {
        int u = (t >= off) ? sm[t - off] : 0;
        __syncthreads();
        sm[t] += u;
        __syncthreads();
    }
    int excl = g_bsum[blockIdx.x] + sm[t] - d;
    if (i < N_NODES) { g_rowptr[i] = excl; g_cursor[i] = excl; }
    if (blockIdx.x == 0 && t == 0) g_rowptr[N_NODES] = E_TOT;
}
__global__ void scatter_kernel() {
    int e = blockIdx.x * blockDim.x + threadIdx.x;
    if (e >= E_TOT) return;
    int d = g_dst[e];
    int pos = atomicAdd(&g_cursor[d], 1);
    g_csr_src[pos] = g_src[e];
}

// ---------------- fp32 -> bf16 hi/lo split (layer-0 input only) --------------
__global__ void split_kernel(const float* __restrict__ src, int total4) {
    int i = blockIdx.x * blockDim.x + threadIdx.x;
    if (i >= total4) return;
    float4 v = ((const float4*)src)[i];
    __nv_bfloat16 h0 = __float2bfloat16(v.x), h1 = __float2bfloat16(v.y);
    __nv_bfloat16 h2 = __float2bfloat16(v.z), h3 = __float2bfloat16(v.w);
    __nv_bfloat16 l0 = __float2bfloat16(v.x - __bfloat162float(h0));
    __nv_bfloat16 l1 = __float2bfloat16(v.y - __bfloat162float(h1));
    __nv_bfloat16 l2 = __float2bfloat16(v.z - __bfloat162float(h2));
    __nv_bfloat16 l3 = __float2bfloat16(v.w - __bfloat162float(h3));
    ((__nv_bfloat162*)g_Ahi)[2 * i + 0] = __nv_bfloat162(h0, h1);
    ((__nv_bfloat162*)g_Ahi)[2 * i + 1] = __nv_bfloat162(h2, h3);
    ((__nv_bfloat162*)g_Alo)[2 * i + 0] = __nv_bfloat162(l0, l1);
    ((__nv_bfloat162*)g_Alo)[2 * i + 1] = __nv_bfloat162(l2, l3);
}
// transpose W[K,N] -> Whi/Wlo [N,K]
__global__ void wsplit_kernel(const float* __restrict__ W, int K, int N) {
    int idx = blockIdx.x * blockDim.x + threadIdx.x;
    if (idx >= K * N) return;
    int n = idx / K, k = idx - n * K;
    float v = W[(size_t)k * N + n];
    __nv_bfloat16 h = __float2bfloat16(v);
    g_Whi[idx] = h;
    g_Wlo[idx] = __float2bfloat16(v - __bfloat162float(h));
}

// ---------------- HMMA bf16 GEMM (3-pass split, cp.async pipelined) ----------
// D[M,N] = Ahi@Whi^T + Ahi@Wlo^T + Alo@Whi^T; A [M,K] K-major, W^T [N,K] K-major.
template <int BN>
__global__ __launch_bounds__(256, 1) void mma_gemm_kernel(float* __restrict__ D,
                                                          int M, int N, int K) {
    extern __shared__ __align__(1024) char smem[];
    char* Abuf[2] = { smem, smem + 16384 };
    char* Bbuf[2] = { smem + 32768, smem + 32768 + BN * 128 };

    const int tid = threadIdx.x;
    const int wid = tid >> 5, lane = tid & 31;
    const int rowBase = blockIdx.y * 128;
    const int colBase = blockIdx.x * BN;
    const int wr = wid >> 2, wc = wid & 3;      // warp grid 2 x 4
    constexpr int WN = BN / 4;
    constexpr int NT = WN / 8;
    const int warpRow = wr * 64, warpCol = wc * WN;

    float acc[4][NT][4];
#pragma unroll
    for (int i = 0; i < 4; i++)
#pragma unroll
        for (int j = 0; j < NT; j++)
#pragma unroll
            for (int q = 0; q < 4; q++) acc[i][j][q] = 0.f;

    const int kch = K / 64;
    const int NCH = 3 * kch;

    auto load_async = [&](int i, char* sA, char* sB) {
        int pass = i / kch, kc = i - pass * kch;
        const __nv_bfloat16* Asrc = (pass == 2) ? g_Alo : g_Ahi;
        const __nv_bfloat16* Bsrc = (pass == 1) ? g_Wlo : g_Whi;
        uint32_t sAu = smem_u32(sA), sBu = smem_u32(sB);
#pragma unroll
        for (int j = 0; j < 4; j++) {                 // A: 128 rows x 8 x 16B
            int q = tid + j * 256;
            int r = q >> 3, c16 = q & 7;
            const void* src = Asrc + (size_t)(rowBase + r) * K + kc * 64 + c16 * 8;
            int bytes = (rowBase + r < M) ? 16 : 0;
            CP_ASYNC16(sAu + sw128(r * 128 + c16 * 16), src, bytes);
        }
#pragma unroll
        for (int j = 0; j < BN / 32; j++) {           // B: BN rows x 8 x 16B
            int q = tid + j * 256;
            int r = q >> 3, c16 = q & 7;
            const void* src = Bsrc + (size_t)(colBase + r) * K + kc * 64 + c16 * 8;
            CP_ASYNC16(sBu + sw128(r * 128 + c16 * 16), src, 16);
        }
        CP_COMMIT();
    };

    load_async(0, Abuf[0], Bbuf[0]);
    CP_WAIT0();
    __syncthreads();

    const int g = lane >> 3;
    const int l7 = lane & 7;

    for (int i = 0; i < NCH; i++) {
        int cur = i & 1;
        if (i + 1 < NCH) load_async(i + 1, Abuf[cur ^ 1], Bbuf[cur ^ 1]);

        uint32_t aBase = smem_u32(Abuf[cur]);
        uint32_t bBase = smem_u32(Bbuf[cur]);
#pragma unroll
        for (int kk = 0; kk < 4; kk++) {
            uint32_t af[4][4];
#pragma unroll
            for (int mt = 0; mt < 4; mt++) {
                int row = warpRow + mt * 16 + l7 + ((g & 1) ? 8 : 0);
                int kb = (kk * 16 + ((g >= 2) ? 8 : 0)) * 2;
                uint32_t addr = aBase + sw128((uint32_t)(row * 128 + kb));
                LDSM_X4(af[mt][0], af[mt][1], af[mt][2], af[mt][3], addr);
            }
            uint32_t bf[NT][2];
#pragma unroll
            for (int np = 0; np < NT / 2; np++) {
                int row = warpCol + np * 16 + l7 + ((g >= 2) ? 8 : 0);
                int kb = (kk * 16 + ((g & 1) ? 8 : 0)) * 2;
                uint32_t addr = bBase + sw128((uint32_t)(row * 128 + kb));
                uint32_t r0, r1, r2, r3;
                LDSM_X4(r0, r1, r2, r3, addr);
                bf[np * 2][0] = r0;  bf[np * 2][1] = r1;
                bf[np * 2 + 1][0] = r2; bf[np * 2 + 1][1] = r3;
            }
#pragma unroll
            for (int mt = 0; mt < 4; mt++)
#pragma unroll
                for (int nt = 0; nt < NT; nt++)
                    mma16816(acc[mt][nt], af[mt], bf[nt]);
        }
        CP_WAIT0();
        __syncthreads();
    }

    // epilogue
    const int qr = lane >> 2, qc = lane & 3;
#pragma unroll
    for (int mt = 0; mt < 4; mt++) {
        int r0 = rowBase + warpRow + mt * 16 + qr;
#pragma unroll
        for (int nt = 0; nt < NT; nt++) {
            int col = colBase + warpCol + nt * 8 + qc * 2;
            if (r0 < M)
                *(float2*)&D[(size_t)r0 * N + col] = make_float2(acc[mt][nt][0], acc[mt][nt][1]);
            if (r0 + 8 < M)
                *(float2*)&D[(size_t)(r0 + 8) * N + col] = make_float2(acc[mt][nt][2], acc[mt][nt][3]);
        }
    }
}

// ---------------- per-(node,head) attention logits ---------------------------
__global__ void node_alpha_kernel(const float* __restrict__ a_s,
                                  const float* __restrict__ a_d,
                                  int H, int C) {
    int warp = (blockIdx.x * blockDim.x + threadIdx.x) >> 5;
    int lane = threadIdx.x & 31;
    if (warp >= N_NODES * H) return;
    int n = warp / H, hh = warp - n * H;
    const float* hv = g_h + (size_t)n * H * C + hh * C;
    float ss = 0.f, sd = 0.f;
    for (int c = lane; c < C; c += 32) {
        float v = hv[c];
        ss += v * a_s[hh * C + c];
        sd += v * a_d[hh * C + c];
    }
#pragma unroll
    for (int o = 16; o; o >>= 1) {
        ss += __shfl_down_sync(0xffffffffu, ss, o);
        sd += __shfl_down_sync(0xffffffffu, sd, o);
    }
    if (lane == 0) { g_asrc[warp] = ss; g_adst[warp] = sd; }
}

// ---------------- per-dst softmax --------------------------------------------
template <int H>
__global__ void attn_alpha_kernel() {
    int d = blockIdx.x;
    int tid = threadIdx.x;
    int lane = tid & 31, wid = tid >> 5;
    int start = g_rowptr[d], end = g_rowptr[d + 1];
    int deg = end - start;

    __shared__ float red[H][4];
    __shared__ float bmax[H], bsum[H];

    float adst[H];
#pragma unroll
    for (int h = 0; h < H; h++) adst[h] = g_adst[d * H + h];

    float lmax[H];
#pragma unroll
    for (int h = 0; h < H; h++) lmax[h] = -INFINITY;
    for (int i = tid; i < deg; i += 128) {
        int s = g_csr_src[start + i];
#pragma unroll
        for (int h = 0; h < H; h++) {
            float v = g_asrc[s * H + h] + adst[h];
            v = (v > 0.f) ? v : 0.2f * v;
            lmax[h] = fmaxf(lmax[h], v);
        }
    }
#pragma unroll
    for (int h = 0; h < H; h++) {
#pragma unroll
        for (int o = 16; o; o >>= 1) lmax[h] = fmaxf(lmax[h], __shfl_down_sync(0xffffffffu, lmax[h], o));
        if (lane == 0) red[h][wid] = lmax[h];
    }
    __syncthreads();
    if (tid < H)
        bmax[tid] = fmaxf(fmaxf(red[tid][0], red[tid][1]), fmaxf(red[tid][2], red[tid][3]));
    __syncthreads();

    float lsum[H];
#pragma unroll
    for (int h = 0; h < H; h++) lsum[h] = 0.f;
    for (int i = tid; i < deg; i += 128) {
        int s = g_csr_src[start + i];
#pragma unroll
        for (int h = 0; h < H; h++) {
            float v = g_asrc[s * H + h] + adst[h];
            v = (v > 0.f) ? v : 0.2f * v;
            lsum[h] += __expf(v - bmax[h]);
        }
    }
#pragma unroll
    for (int h = 0; h < H; h++) {
#pragma unroll
        for (int o = 16; o; o >>= 1) lsum[h] += __shfl_down_sync(0xffffffffu, lsum[h], o);
        if (lane == 0) red[h][wid] = lsum[h];
    }
    __syncthreads();
    if (tid < H) bsum[tid] = 1.f / (red[tid][0] + red[tid][1] + red[tid][2] + red[tid][3]);
    __syncthreads();

    for (int i = tid; i < deg; i += 128) {
        int s = g_csr_src[start + i];
#pragma unroll
        for (int h = 0; h < H; h++) {
            float v = g_asrc[s * H + h] + adst[h];
            v = (v > 0.f) ? v : 0.2f * v;
            g_alpha[(size_t)(start + i) * H + h] = __expf(v - bmax[h]) * bsum[h];
        }
    }
}

// ---------------- gather-aggregate + bias + relu (+ fused bf16 split) --------
template <int H, int C, bool SPLIT>
__global__ void agg_kernel(const float* __restrict__ bias, float* __restrict__ out) {
    constexpr int HC = H * C;
    constexpr int NV = HC / 4;
    int d = blockIdx.x;
    int tid = threadIdx.x;
    if (tid >= NV) return;
    int c4 = tid * 4;
    int head = c4 / C;
    int start = g_rowptr[d], end = g_rowptr[d + 1];

    float4 acc = make_float4(0.f, 0.f, 0.f, 0.f);
    for (int pos = start; pos < end; pos++) {
        int s = g_csr_src[pos];
        float al = g_alpha[(size_t)pos * H + head];
        float4 hv = *(const float4*)&g_h[(size_t)s * HC + c4];
        acc.x += hv.x * al; acc.y += hv.y * al;
        acc.z += hv.z * al; acc.w += hv.w * al;
    }
    float4 bv = *(const float4*)&bias[c4];
    acc.x = fmaxf(acc.x + bv.x, 0.f);
    acc.y = fmaxf(acc.y + bv.y, 0.f);
    acc.z = fmaxf(acc.z + bv.z, 0.f);
    acc.w = fmaxf(acc.w + bv.w, 0.f);
    if (SPLIT) {
        size_t base = (size_t)d * HC + c4;
        __nv_bfloat16 h0 = __float2bfloat16(acc.x), h1 = __float2bfloat16(acc.y);
        __nv_bfloat16 h2 = __float2bfloat16(acc.z), h3 = __float2bfloat16(acc.w);
        __nv_bfloat16 l0 = __float2bfloat16(acc.x - __bfloat162float(h0));
        __nv_bfloat16 l1 = __float2bfloat16(acc.y - __bfloat162float(h1));
        __nv_bfloat16 l2 = __float2bfloat16(acc.z - __bfloat162float(h2));
        __nv_bfloat16 l3 = __float2bfloat16(acc.w - __bfloat162float(h3));
        ((__nv_bfloat162*)(g_Ahi + base))[0] = __nv_bfloat162(h0, h1);
        ((__nv_bfloat162*)(g_Ahi + base))[1] = __nv_bfloat162(h2, h3);
        ((__nv_bfloat162*)(g_Alo + base))[0] = __nv_bfloat162(l0, l1);
        ((__nv_bfloat162*)(g_Alo + base))[1] = __nv_bfloat162(l2, l3);
    } else {
        *(float4*)&out[(size_t)d * HC + c4] = acc;
    }
}

// ---------------- driver ------------------------------------------------------
extern "C" void kernel_launch(void* const* d_in, const int* in_sizes, int n_in,
                              void* d_out, int out_size) {
    const float* x  = (const float*)d_in[0];
    const void*  ei = d_in[1];
    float* out = (float*)d_out;

    void* p;
    cudaGetSymbolAddress(&p, g_h);
    float* h_ptr = (float*)p;

    static bool attr_done = false;
    if (!attr_done) {
        cudaFuncSetAttribute(mma_gemm_kernel<128>, cudaFuncAttributeMaxDynamicSharedMemorySize,
                             2 * 16384 + 2 * 128 * 128);
        cudaFuncSetAttribute(mma_gemm_kernel<64>, cudaFuncAttributeMaxDynamicSharedMemorySize,
                             2 * 16384 + 2 * 64 * 128);
        attr_done = true;
    }

    struct Cfg { const float *W, *as, *ad, *b; int Fin, H, C; };
    Cfg cfg[4] = {
        { (const float*)d_in[2],  (const float*)d_in[3],  (const float*)d_in[4],  (const float*)d_in[5],  256, 4, 128 },
        { (const float*)d_in[6],  (const float*)d_in[7],  (const float*)d_in[8],  (const float*)d_in[9],  512, 4, 128 },
        { (const float*)d_in[10], (const float*)d_in[11], (const float*)d_in[12], (const float*)d_in[13], 512, 4,  64 },
        { (const float*)d_in[14], (const float*)d_in[15], (const float*)d_in[16], (const float*)d_in[17], 256, 1,  64 },
    };

    detect_dtype_kernel<<<1, 1>>>((const int*)ei);
    zero_deg_kernel<<<(N_NODES + TPB - 1) / TPB, TPB>>>();
    build_edges_kernel<<<(E_TOT + TPB - 1) / TPB, TPB>>>(ei);
    scan1_kernel<<<NSB, SB>>>();
    scan2_kernel<<<1, 256>>>();
    scan3_kernel<<<NSB, SB>>>();
    scatter_kernel<<<(E_TOT + TPB - 1) / TPB, TPB>>>();

    // layer-0 input split (later layers: agg writes bf16 hi/lo directly)
    {
        int total4 = N_NODES * 256 / 4;
        split_kernel<<<(total4 + TPB - 1) / TPB, TPB>>>(x, total4);
    }

    const int MT = (N_NODES + 127) / 128;

    for (int L = 0; L < 4; L++) {
        const Cfg& c = cfg[L];
        int HC = c.H * c.C;

        wsplit_kernel<<<(c.Fin * HC + TPB - 1) / TPB, TPB>>>(c.W, c.Fin, HC);

        if (HC >= 128) {
            dim3 grid(HC / 128, MT);
            mma_gemm_kernel<128><<<grid, 256, 2 * 16384 + 2 * 128 * 128>>>(h_ptr, N_NODES, HC, c.Fin);
        } else {
            dim3 grid(HC / 64, MT);
            mma_gemm_kernel<64><<<grid, 256, 2 * 16384 + 2 * 64 * 128>>>(h_ptr, N_NODES, HC, c.Fin);
        }

        int nwarps = N_NODES * c.H;
        node_alpha_kernel<<<(nwarps * 32 + TPB - 1) / TPB, TPB>>>(c.as, c.ad, c.H, c.C);

        switch (L) {
            case 0:
                attn_alpha_kernel<4><<<N_NODES, 128>>>();
                agg_kernel<4, 128, true><<<N_NODES, 128>>>(c.b, nullptr);
                break;
            case 1:
                attn_alpha_kernel<4><<<N_NODES, 128>>>();
                agg_kernel<4, 128, true><<<N_NODES, 128>>>(c.b, nullptr);
                break;
            case 2:
                attn_alpha_kernel<4><<<N_NODES, 128>>>();
                agg_kernel<4, 64, true><<<N_NODES, 64>>>(c.b, nullptr);
                break;
            case 3:
                attn_alpha_kernel<1><<<N_NODES, 128>>>();
                agg_kernel<1, 64, false><<<N_NODES, 32>>>(c.b, out);
                break;
        }
    }
}

// round 7
// speedup vs baseline: 1.8871x; 1.0593x over previous
#include <cuda_runtime.h>
#include <cuda_bf16.h>
#include <math.h>
#include <stdint.h>

#define N_NODES 30000
#define E_RAW   480000
#define E_TOT   (E_RAW + N_NODES)
#define MAXH    4
#define MAXHC   512
#define TPB     256
#define MAXK    512

// ---------------- scratch ----------------------------------------------------
__device__ float g_h[N_NODES * MAXHC];
__device__ float g_asrc[N_NODES * MAXH];
__device__ float g_adst[N_NODES * MAXH];
__device__ float g_alpha[E_TOT * MAXH];
__device__ int   g_src[E_TOT];
__device__ int   g_dst[E_TOT];
__device__ int   g_csr_src[E_TOT];
__device__ int   g_deg[N_NODES];
__device__ int   g_rowptr[N_NODES + 1];
__device__ int   g_cursor[N_NODES];
__device__ int   g_is64;
__device__ __align__(16) __nv_bfloat16 g_Ahi[N_NODES * MAXK];
__device__ __align__(16) __nv_bfloat16 g_Alo[N_NODES * MAXK];
__device__ __align__(16) __nv_bfloat16 g_Whi[MAXK * MAXHC];   // [N,K] transposed
__device__ __align__(16) __nv_bfloat16 g_Wlo[MAXK * MAXHC];
#define SB 128
#define NSB ((N_NODES + SB - 1) / SB)
__device__ int g_bsum[NSB];

// ---------------- helpers -----------------------------------------------------
__device__ __forceinline__ uint32_t smem_u32(const void* p) {
    uint32_t a;
    asm("{ .reg .u64 t; cvta.to.shared.u64 t, %1; cvt.u32.u64 %0, t; }" : "=r"(a) : "l"(p));
    return a;
}
__device__ __forceinline__ uint32_t sw128(uint32_t off) { return off ^ ((off >> 3) & 0x70); }
__device__ __forceinline__ int clampN(int v) {
    return v < 0 ? 0 : (v >= N_NODES ? N_NODES - 1 : v);
}
#define LDSM_X4(r0, r1, r2, r3, addr) \
    asm volatile("ldmatrix.sync.aligned.m8n8.x4.shared.b16 {%0,%1,%2,%3}, [%4];" \
                 : "=r"(r0), "=r"(r1), "=r"(r2), "=r"(r3) : "r"(addr))
#define CP_ASYNC16(saddr, gptr, bytes) \
    asm volatile("cp.async.cg.shared.global [%0], [%1], 16, %2;" \
                 :: "r"(saddr), "l"(gptr), "r"(bytes))
#define CP_COMMIT()  asm volatile("cp.async.commit_group;" ::: "memory")
#define CP_WAIT0()   asm volatile("cp.async.wait_group 0;" ::: "memory")
__device__ __forceinline__ void mma16816(float* c, const uint32_t* a, const uint32_t* b) {
    asm volatile(
        "mma.sync.aligned.m16n8k16.row.col.f32.bf16.bf16.f32 "
        "{%0,%1,%2,%3}, {%4,%5,%6,%7}, {%8,%9}, {%0,%1,%2,%3};"
        : "+f"(c[0]), "+f"(c[1]), "+f"(c[2]), "+f"(c[3])
        : "r"(a[0]), "r"(a[1]), "r"(a[2]), "r"(a[3]), "r"(b[0]), "r"(b[1]));
}

// ---------------- preprocessing ----------------------------------------------
__global__ void detect_dtype_kernel(const int* __restrict__ ei32) {
    int all_odd_zero = 1;
    for (int i = 0; i < 32; i++)
        if (ei32[2 * i + 1] != 0) { all_odd_zero = 0; break; }
    g_is64 = all_odd_zero;
}
__global__ void zero_deg_kernel() {
    int i = blockIdx.x * blockDim.x + threadIdx.x;
    if (i < N_NODES) g_deg[i] = 0;
}
__global__ void build_edges_kernel(const void* __restrict__ ei_raw) {
    int i = blockIdx.x * blockDim.x + threadIdx.x;
    if (i >= E_TOT) return;
    int s, d;
    if (i < E_RAW) {
        if (g_is64) {
            const long long* e = (const long long*)ei_raw;
            s = (int)e[i]; d = (int)e[E_RAW + i];
        } else {
            const int* e = (const int*)ei_raw;
            s = e[i]; d = e[E_RAW + i];
        }
        s = clampN(s); d = clampN(d);
    } else {
        s = i - E_RAW; d = s;
    }
    g_src[i] = s; g_dst[i] = d;
    atomicAdd(&g_deg[d], 1);
}
__global__ void scan1_kernel() {
    __shared__ int sm[SB];
    int i = blockIdx.x * SB + threadIdx.x;
    sm[threadIdx.x] = (i < N_NODES) ? g_deg[i] : 0;
    __syncthreads();
    for (int off = SB / 2; off > 0; off >>= 1) {
        if (threadIdx.x < off) sm[threadIdx.x] += sm[threadIdx.x + off];
        __syncthreads();
    }
    if (threadIdx.x == 0) g_bsum[blockIdx.x] = sm[0];
}
__global__ void scan2_kernel() {
    __shared__ int sm[256];
    int t = threadIdx.x;
    int v = (t < NSB) ? g_bsum[t] : 0;
    sm[t] = v;
    __syncthreads();
    for (int off = 1; off < 256; off <<= 1) {
        int u = (t >= off) ? sm[t - off] : 0;
        __syncthreads();
        sm[t] += u;
        __syncthreads();
    }
    if (t < NSB) g_bsum[t] = sm[t] - v;
}
__global__ void scan3_kernel() {
    __shared__ int sm[SB];
    int t = threadIdx.x;
    int i = blockIdx.x * SB + t;
    int d = (i < N_NODES) ? g_deg[i] : 0;
    sm[t] = d;
    __syncthreads();
    for (int off = 1; off < SB; off <<= 1) {
        int u = (t >= off) ? sm[t - off] : 0;
        __syncthreads();
        sm[t] += u;
        __syncthreads();
    }
    int excl = g_bsum[blockIdx.x] + sm[t] - d;
    if (i < N_NODES) { g_rowptr[i] = excl; g_cursor[i] = excl; }
    if (blockIdx.x == 0 && t == 0) g_rowptr[N_NODES] = E_TOT;
}
__global__ void scatter_kernel() {
    int e = blockIdx.x * blockDim.x + threadIdx.x;
    if (e >= E_TOT) return;
    int d = g_dst[e];
    int pos = atomicAdd(&g_cursor[d], 1);
    g_csr_src[pos] = g_src[e];
}

// ---------------- fp32 -> bf16 hi/lo split (layer-0 input only) --------------
__global__ void split_kernel(const float* __restrict__ src, int total4) {
    int i = blockIdx.x * blockDim.x + threadIdx.x;
    if (i >= total4) return;
    float4 v = ((const float4*)src)[i];
    __nv_bfloat16 h0 = __float2bfloat16(v.x), h1 = __float2bfloat16(v.y);
    __nv_bfloat16 h2 = __float2bfloat16(v.z), h3 = __float2bfloat16(v.w);
    __nv_bfloat16 l0 = __float2bfloat16(v.x - __bfloat162float(h0));
    __nv_bfloat16 l1 = __float2bfloat16(v.y - __bfloat162float(h1));
    __nv_bfloat16 l2 = __float2bfloat16(v.z - __bfloat162float(h2));
    __nv_bfloat16 l3 = __float2bfloat16(v.w - __bfloat162float(h3));
    ((__nv_bfloat162*)g_Ahi)[2 * i + 0] = __nv_bfloat162(h0, h1);
    ((__nv_bfloat162*)g_Ahi)[2 * i + 1] = __nv_bfloat162(h2, h3);
    ((__nv_bfloat162*)g_Alo)[2 * i + 0] = __nv_bfloat162(l0, l1);
    ((__nv_bfloat162*)g_Alo)[2 * i + 1] = __nv_bfloat162(l2, l3);
}
// coalesced transpose+split: W[K,N] -> Whi/Wlo [N,K] via 32x32 smem tiles
__global__ void wsplit_kernel(const float* __restrict__ W, int K, int N) {
    __shared__ float t[32][33];
    int nb = blockIdx.x * 32, kb = blockIdx.y * 32;
    int tx = threadIdx.x, ty = threadIdx.y;   // (32, 8)
#pragma unroll
    for (int j = 0; j < 4; j++)
        t[ty + j * 8][tx] = W[(size_t)(kb + ty + j * 8) * N + nb + tx];
    __syncthreads();
#pragma unroll
    for (int j = 0; j < 4; j++) {
        int n = nb + ty + j * 8, k = kb + tx;
        float v = t[tx][ty + j * 8];
        __nv_bfloat16 h = __float2bfloat16(v);
        g_Whi[(size_t)n * K + k] = h;
        g_Wlo[(size_t)n * K + k] = __float2bfloat16(v - __bfloat162float(h));
    }
}

// ---------------- HMMA bf16 GEMM (3-pass split, cp.async, fused alpha) -------
// D[M,N] = Ahi@Whi^T + Ahi@Wlo^T + Alo@Whi^T; also writes
// g_asrc/g_adst[row, head] = dot(D_row_head, a_s/a_d) in the epilogue.
template <int BN>
__global__ __launch_bounds__(256, 1) void mma_gemm_kernel(
        float* __restrict__ D, const float* __restrict__ a_s,
        const float* __restrict__ a_d, int M, int N, int K, int H, int C) {
    extern __shared__ __align__(1024) char smem[];
    char* Abuf[2] = { smem, smem + 16384 };
    char* Bbuf[2] = { smem + 32768, smem + 32768 + BN * 128 };

    const int tid = threadIdx.x;
    const int wid = tid >> 5, lane = tid & 31;
    const int rowBase = blockIdx.y * 128;
    const int colBase = blockIdx.x * BN;
    const int wr = wid >> 2, wc = wid & 3;      // warp grid 2 x 4
    constexpr int WN = BN / 4;
    constexpr int NT = WN / 8;
    const int warpRow = wr * 64, warpCol = wc * WN;

    float acc[4][NT][4];
#pragma unroll
    for (int i = 0; i < 4; i++)
#pragma unroll
        for (int j = 0; j < NT; j++)
#pragma unroll
            for (int q = 0; q < 4; q++) acc[i][j][q] = 0.f;

    const int kch = K / 64;
    const int NCH = 3 * kch;

    auto load_async = [&](int i, char* sA, char* sB) {
        int pass = i / kch, kc = i - pass * kch;
        const __nv_bfloat16* Asrc = (pass == 2) ? g_Alo : g_Ahi;
        const __nv_bfloat16* Bsrc = (pass == 1) ? g_Wlo : g_Whi;
        uint32_t sAu = smem_u32(sA), sBu = smem_u32(sB);
#pragma unroll
        for (int j = 0; j < 4; j++) {
            int q = tid + j * 256;
            int r = q >> 3, c16 = q & 7;
            const void* src = Asrc + (size_t)(rowBase + r) * K + kc * 64 + c16 * 8;
            int bytes = (rowBase + r < M) ? 16 : 0;
            CP_ASYNC16(sAu + sw128(r * 128 + c16 * 16), src, bytes);
        }
#pragma unroll
        for (int j = 0; j < BN / 32; j++) {
            int q = tid + j * 256;
            int r = q >> 3, c16 = q & 7;
            const void* src = Bsrc + (size_t)(colBase + r) * K + kc * 64 + c16 * 8;
            CP_ASYNC16(sBu + sw128(r * 128 + c16 * 16), src, 16);
        }
        CP_COMMIT();
    };

    load_async(0, Abuf[0], Bbuf[0]);
    CP_WAIT0();
    __syncthreads();

    const int g = lane >> 3;
    const int l7 = lane & 7;

    for (int i = 0; i < NCH; i++) {
        int cur = i & 1;
        if (i + 1 < NCH) load_async(i + 1, Abuf[cur ^ 1], Bbuf[cur ^ 1]);

        uint32_t aBase = smem_u32(Abuf[cur]);
        uint32_t bBase = smem_u32(Bbuf[cur]);
#pragma unroll
        for (int kk = 0; kk < 4; kk++) {
            uint32_t af[4][4];
#pragma unroll
            for (int mt = 0; mt < 4; mt++) {
                int row = warpRow + mt * 16 + l7 + ((g & 1) ? 8 : 0);
                int kb = (kk * 16 + ((g >= 2) ? 8 : 0)) * 2;
                uint32_t addr = aBase + sw128((uint32_t)(row * 128 + kb));
                LDSM_X4(af[mt][0], af[mt][1], af[mt][2], af[mt][3], addr);
            }
            uint32_t bf[NT][2];
#pragma unroll
            for (int np = 0; np < NT / 2; np++) {
                int row = warpCol + np * 16 + l7 + ((g >= 2) ? 8 : 0);
                int kb = (kk * 16 + ((g & 1) ? 8 : 0)) * 2;
                uint32_t addr = bBase + sw128((uint32_t)(row * 128 + kb));
                uint32_t r0, r1, r2, r3;
                LDSM_X4(r0, r1, r2, r3, addr);
                bf[np * 2][0] = r0;  bf[np * 2][1] = r1;
                bf[np * 2 + 1][0] = r2; bf[np * 2 + 1][1] = r3;
            }
#pragma unroll
            for (int mt = 0; mt < 4; mt++)
#pragma unroll
                for (int nt = 0; nt < NT; nt++)
                    mma16816(acc[mt][nt], af[mt], bf[nt]);
        }
        CP_WAIT0();
        __syncthreads();
    }

    // ---------------- epilogue: store D + fused alpha dots -------------------
    const int qr = lane >> 2, qc = lane & 3;
#pragma unroll
    for (int mt = 0; mt < 4; mt++) {
        int r0 = rowBase + warpRow + mt * 16 + qr;
#pragma unroll
        for (int nt = 0; nt < NT; nt++) {
            int col = colBase + warpCol + nt * 8 + qc * 2;
            if (r0 < M)
                *(float2*)&D[(size_t)r0 * N + col] = make_float2(acc[mt][nt][0], acc[mt][nt][1]);
            if (r0 + 8 < M)
                *(float2*)&D[(size_t)(r0 + 8) * N + col] = make_float2(acc[mt][nt][2], acc[mt][nt][3]);
        }
    }

    // reuse smem (mainloop done): sAs[BN], sAd[BN], sRedS[4][128], sRedD[4][128]
    float* sAs   = (float*)smem;
    float* sAd   = sAs + BN;
    float* sRedS = sAd + BN;
    float* sRedD = sRedS + 4 * 128;
    if (tid < BN) {            // a_s/a_d flat [H*C]: flat idx == global col idx
        sAs[tid] = a_s[colBase + tid];
        sAd[tid] = a_d[colBase + tid];
    }
    __syncthreads();

#pragma unroll
    for (int mt = 0; mt < 4; mt++) {
        float s0 = 0.f, s1 = 0.f, d0 = 0.f, d1 = 0.f;
#pragma unroll
        for (int nt = 0; nt < NT; nt++) {
#pragma unroll
            for (int q = 0; q < 2; q++) {
                int cl = warpCol + nt * 8 + qc * 2 + q;
                float as = sAs[cl], ad = sAd[cl];
                s0 += acc[mt][nt][q] * as;     d0 += acc[mt][nt][q] * ad;
                s1 += acc[mt][nt][2 + q] * as; d1 += acc[mt][nt][2 + q] * ad;
            }
        }
#pragma unroll
        for (int o = 2; o; o >>= 1) {
            s0 += __shfl_down_sync(0xffffffffu, s0, o, 4);
            s1 += __shfl_down_sync(0xffffffffu, s1, o, 4);
            d0 += __shfl_down_sync(0xffffffffu, d0, o, 4);
            d1 += __shfl_down_sync(0xffffffffu, d1, o, 4);
        }
        if (qc == 0) {
            int rl = warpRow + mt * 16 + qr;
            sRedS[wc * 128 + rl] = s0;  sRedS[wc * 128 + rl + 8] = s1;
            sRedD[wc * 128 + rl] = d0;  sRedD[wc * 128 + rl + 8] = d1;
        }
    }
    __syncthreads();

    if (tid < 128) {
        int grow = rowBase + tid;
        if (grow < M) {
            int hpb = (BN > C) ? (BN / C) : 1;   // heads per block (1 or 2)
            int wph = 4 / hpb;                    // warp-cols per head
            int headBase = colBase / C;
            for (int hh = 0; hh < hpb; hh++) {
                float as = 0.f, ad = 0.f;
                for (int w = 0; w < wph; w++) {
                    as += sRedS[(hh * wph + w) * 128 + tid];
                    ad += sRedD[(hh * wph + w) * 128 + tid];
                }
                g_asrc[grow * H + headBase + hh] = as;
                g_adst[grow * H + headBase + hh] = ad;
            }
        }
    }
}

// ---------------- per-dst softmax --------------------------------------------
template <int H>
__global__ void attn_alpha_kernel() {
    int d = blockIdx.x;
    int tid = threadIdx.x;
    int lane = tid & 31, wid = tid >> 5;
    int start = g_rowptr[d], end = g_rowptr[d + 1];
    int deg = end - start;

    __shared__ float red[H][4];
    __shared__ float bmax[H], bsum[H];

    float adst[H];
#pragma unroll
    for (int h = 0; h < H; h++) adst[h] = g_adst[d * H + h];

    float lmax[H];
#pragma unroll
    for (int h = 0; h < H; h++) lmax[h] = -INFINITY;
    for (int i = tid; i < deg; i += 128) {
        int s = g_csr_src[start + i];
#pragma unroll
        for (int h = 0; h < H; h++) {
            float v = g_asrc[s * H + h] + adst[h];
            v = (v > 0.f) ? v : 0.2f * v;
            lmax[h] = fmaxf(lmax[h], v);
        }
    }
#pragma unroll
    for (int h = 0; h < H; h++) {
#pragma unroll
        for (int o = 16; o; o >>= 1) lmax[h] = fmaxf(lmax[h], __shfl_down_sync(0xffffffffu, lmax[h], o));
        if (lane == 0) red[h][wid] = lmax[h];
    }
    __syncthreads();
    if (tid < H)
        bmax[tid] = fmaxf(fmaxf(red[tid][0], red[tid][1]), fmaxf(red[tid][2], red[tid][3]));
    __syncthreads();

    float lsum[H];
#pragma unroll
    for (int h = 0; h < H; h++) lsum[h] = 0.f;
    for (int i = tid; i < deg; i += 128) {
        int s = g_csr_src[start + i];
#pragma unroll
        for (int h = 0; h < H; h++) {
            float v = g_asrc[s * H + h] + adst[h];
            v = (v > 0.f) ? v : 0.2f * v;
            lsum[h] += __expf(v - bmax[h]);
        }
    }
#pragma unroll
    for (int h = 0; h < H; h++) {
#pragma unroll
        for (int o = 16; o; o >>= 1) lsum[h] += __shfl_down_sync(0xffffffffu, lsum[h], o);
        if (lane == 0) red[h][wid] = lsum[h];
    }
    __syncthreads();
    if (tid < H) bsum[tid] = 1.f / (red[tid][0] + red[tid][1] + red[tid][2] + red[tid][3]);
    __syncthreads();

    for (int i = tid; i < deg; i += 128) {
        int s = g_csr_src[start + i];
#pragma unroll
        for (int h = 0; h < H; h++) {
            float v = g_asrc[s * H + h] + adst[h];
            v = (v > 0.f) ? v : 0.2f * v;
            g_alpha[(size_t)(start + i) * H + h] = __expf(v - bmax[h]) * bsum[h];
        }
    }
}

// ---------------- gather-aggregate + bias + relu (+ fused bf16 split) --------
template <int H, int C, bool SPLIT>
__global__ void agg_kernel(const float* __restrict__ bias, float* __restrict__ out) {
    constexpr int HC = H * C;
    constexpr int NV = HC / 4;
    int d = blockIdx.x;
    int tid = threadIdx.x;
    if (tid >= NV) return;
    int c4 = tid * 4;
    int head = c4 / C;
    int start = g_rowptr[d], end = g_rowptr[d + 1];

    float4 acc = make_float4(0.f, 0.f, 0.f, 0.f);
    for (int pos = start; pos < end; pos++) {
        int s = g_csr_src[pos];
        float al = g_alpha[(size_t)pos * H + head];
        float4 hv = *(const float4*)&g_h[(size_t)s * HC + c4];
        acc.x += hv.x * al; acc.y += hv.y * al;
        acc.z += hv.z * al; acc.w += hv.w * al;
    }
    float4 bv = *(const float4*)&bias[c4];
    acc.x = fmaxf(acc.x + bv.x, 0.f);
    acc.y = fmaxf(acc.y + bv.y, 0.f);
    acc.z = fmaxf(acc.z + bv.z, 0.f);
    acc.w = fmaxf(acc.w + bv.w, 0.f);
    if (SPLIT) {
        size_t base = (size_t)d * HC + c4;
        __nv_bfloat16 h0 = __float2bfloat16(acc.x), h1 = __float2bfloat16(acc.y);
        __nv_bfloat16 h2 = __float2bfloat16(acc.z), h3 = __float2bfloat16(acc.w);
        __nv_bfloat16 l0 = __float2bfloat16(acc.x - __bfloat162float(h0));
        __nv_bfloat16 l1 = __float2bfloat16(acc.y - __bfloat162float(h1));
        __nv_bfloat16 l2 = __float2bfloat16(acc.z - __bfloat162float(h2));
        __nv_bfloat16 l3 = __float2bfloat16(acc.w - __bfloat162float(h3));
        ((__nv_bfloat162*)(g_Ahi + base))[0] = __nv_bfloat162(h0, h1);
        ((__nv_bfloat162*)(g_Ahi + base))[1] = __nv_bfloat162(h2, h3);
        ((__nv_bfloat162*)(g_Alo + base))[0] = __nv_bfloat162(l0, l1);
        ((__nv_bfloat162*)(g_Alo + base))[1] = __nv_bfloat162(l2, l3);
    } else {
        *(float4*)&out[(size_t)d * HC + c4] = acc;
    }
}

// ---------------- driver ------------------------------------------------------
extern "C" void kernel_launch(void* const* d_in, const int* in_sizes, int n_in,
                              void* d_out, int out_size) {
    const float* x  = (const float*)d_in[0];
    const void*  ei = d_in[1];
    float* out = (float*)d_out;

    void* p;
    cudaGetSymbolAddress(&p, g_h);
    float* h_ptr = (float*)p;

    static bool attr_done = false;
    if (!attr_done) {
        cudaFuncSetAttribute(mma_gemm_kernel<128>, cudaFuncAttributeMaxDynamicSharedMemorySize,
                             2 * 16384 + 2 * 128 * 128);
        cudaFuncSetAttribute(mma_gemm_kernel<64>, cudaFuncAttributeMaxDynamicSharedMemorySize,
                             2 * 16384 + 2 * 64 * 128);
        attr_done = true;
    }

    struct Cfg { const float *W, *as, *ad, *b; int Fin, H, C; };
    Cfg cfg[4] = {
        { (const float*)d_in[2],  (const float*)d_in[3],  (const float*)d_in[4],  (const float*)d_in[5],  256, 4, 128 },
        { (const float*)d_in[6],  (const float*)d_in[7],  (const float*)d_in[8],  (const float*)d_in[9],  512, 4, 128 },
        { (const float*)d_in[10], (const float*)d_in[11], (const float*)d_in[12], (const float*)d_in[13], 512, 4,  64 },
        { (const float*)d_in[14], (const float*)d_in[15], (const float*)d_in[16], (const float*)d_in[17], 256, 1,  64 },
    };

    detect_dtype_kernel<<<1, 1>>>((const int*)ei);
    zero_deg_kernel<<<(N_NODES + TPB - 1) / TPB, TPB>>>();
    build_edges_kernel<<<(E_TOT + TPB - 1) / TPB, TPB>>>(ei);
    scan1_kernel<<<NSB, SB>>>();
    scan2_kernel<<<1, 256>>>();
    scan3_kernel<<<NSB, SB>>>();
    scatter_kernel<<<(E_TOT + TPB - 1) / TPB, TPB>>>();

    {
        int total4 = N_NODES * 256 / 4;
        split_kernel<<<(total4 + TPB - 1) / TPB, TPB>>>(x, total4);
    }

    const int MT = (N_NODES + 127) / 128;

    for (int L = 0; L < 4; L++) {
        const Cfg& c = cfg[L];
        int HC = c.H * c.C;

        {
            dim3 wgrid(HC / 32, c.Fin / 32);
            wsplit_kernel<<<wgrid, dim3(32, 8)>>>(c.W, c.Fin, HC);
        }

        if (HC >= 128) {
            dim3 grid(HC / 128, MT);
            mma_gemm_kernel<128><<<grid, 256, 2 * 16384 + 2 * 128 * 128>>>(
                h_ptr, c.as, c.ad, N_NODES, HC, c.Fin, c.H, c.C);
        } else {
            dim3 grid(HC / 64, MT);
            mma_gemm_kernel<64><<<grid, 256, 2 * 16384 + 2 * 64 * 128>>>(
                h_ptr, c.as, c.ad, N_NODES, HC, c.Fin, c.H, c.C);
        }

        switch (L) {
            case 0:
                attn_alpha_kernel<4><<<N_NODES, 128>>>();
                agg_kernel<4, 128, true><<<N_NODES, 128>>>(c.b, nullptr);
                break;
            case 1:
                attn_alpha_kernel<4><<<N_NODES, 128>>>();
                agg_kernel<4, 128, true><<<N_NODES, 128>>>(c.b, nullptr);
                break;
            case 2:
                attn_alpha_kernel<4><<<N_NODES, 128>>>();
                agg_kernel<4, 64, true><<<N_NODES, 64>>>(c.b, nullptr);
                break;
            case 3:
                attn_alpha_kernel<1><<<N_NODES, 128>>>();
                agg_kernel<1, 64, false><<<N_NODES, 32>>>(c.b, out);
                break;
        }
    }
}

// round 8
// speedup vs baseline: 2.4136x; 1.2790x over previous
#include <cuda_runtime.h>
#include <cuda_bf16.h>
#include <math.h>
#include <stdint.h>

#define N_NODES 30000
#define E_RAW   480000
#define E_TOT   (E_RAW + N_NODES)
#define MAXH    4
#define MAXHC   512
#define TPB     256
#define MAXK    512

// ---------------- scratch ----------------------------------------------------
__device__ float g_h[N_NODES * MAXHC];
__device__ float g_asrc[N_NODES * MAXH];
__device__ float g_adst[N_NODES * MAXH];
__device__ float g_emax[N_NODES * MAXH];    // per-(node,head) softmax max
__device__ float g_invd[N_NODES * MAXH];    // per-(node,head) 1/denominator
__device__ int   g_src[E_TOT];
__device__ int   g_dst[E_TOT];
__device__ int   g_csr_src[E_TOT];
__device__ int   g_deg[N_NODES];
__device__ int   g_rowptr[N_NODES + 1];
__device__ int   g_cursor[N_NODES];
__device__ int   g_is64;
__device__ __align__(16) __nv_bfloat16 g_Ahi[N_NODES * MAXK];
__device__ __align__(16) __nv_bfloat16 g_Alo[N_NODES * MAXK];
__device__ __align__(16) __nv_bfloat16 g_Whi[MAXK * MAXHC];   // [N,K] transposed
__device__ __align__(16) __nv_bfloat16 g_Wlo[MAXK * MAXHC];
#define SB 128
#define NSB ((N_NODES + SB - 1) / SB)
__device__ int g_bsum[NSB];

// ---------------- helpers -----------------------------------------------------
__device__ __forceinline__ uint32_t smem_u32(const void* p) {
    uint32_t a;
    asm("{ .reg .u64 t; cvta.to.shared.u64 t, %1; cvt.u32.u64 %0, t; }" : "=r"(a) : "l"(p));
    return a;
}
__device__ __forceinline__ uint32_t sw128(uint32_t off) { return off ^ ((off >> 3) & 0x70); }
__device__ __forceinline__ int clampN(int v) {
    return v < 0 ? 0 : (v >= N_NODES ? N_NODES - 1 : v);
}
#define LDSM_X4(r0, r1, r2, r3, addr) \
    asm volatile("ldmatrix.sync.aligned.m8n8.x4.shared.b16 {%0,%1,%2,%3}, [%4];" \
                 : "=r"(r0), "=r"(r1), "=r"(r2), "=r"(r3) : "r"(addr))
#define CP_ASYNC16(saddr, gptr, bytes) \
    asm volatile("cp.async.cg.shared.global [%0], [%1], 16, %2;" \
                 :: "r"(saddr), "l"(gptr), "r"(bytes))
#define CP_COMMIT()  asm volatile("cp.async.commit_group;" ::: "memory")
#define CP_WAIT0()   asm volatile("cp.async.wait_group 0;" ::: "memory")
__device__ __forceinline__ void mma16816(float* c, const uint32_t* a, const uint32_t* b) {
    asm volatile(
        "mma.sync.aligned.m16n8k16.row.col.f32.bf16.bf16.f32 "
        "{%0,%1,%2,%3}, {%4,%5,%6,%7}, {%8,%9}, {%0,%1,%2,%3};"
        : "+f"(c[0]), "+f"(c[1]), "+f"(c[2]), "+f"(c[3])
        : "r"(a[0]), "r"(a[1]), "r"(a[2]), "r"(a[3]), "r"(b[0]), "r"(b[1]));
}

// ---------------- preprocessing ----------------------------------------------
__global__ void detect_dtype_kernel(const int* __restrict__ ei32) {
    int all_odd_zero = 1;
    for (int i = 0; i < 32; i++)
        if (ei32[2 * i + 1] != 0) { all_odd_zero = 0; break; }
    g_is64 = all_odd_zero;
}
__global__ void zero_deg_kernel() {
    int i = blockIdx.x * blockDim.x + threadIdx.x;
    if (i < N_NODES) g_deg[i] = 0;
}
__global__ void build_edges_kernel(const void* __restrict__ ei_raw) {
    int i = blockIdx.x * blockDim.x + threadIdx.x;
    if (i >= E_TOT) return;
    int s, d;
    if (i < E_RAW) {
        if (g_is64) {
            const long long* e = (const long long*)ei_raw;
            s = (int)e[i]; d = (int)e[E_RAW + i];
        } else {
            const int* e = (const int*)ei_raw;
            s = e[i]; d = e[E_RAW + i];
        }
        s = clampN(s); d = clampN(d);
    } else {
        s = i - E_RAW; d = s;
    }
    g_src[i] = s; g_dst[i] = d;
    atomicAdd(&g_deg[d], 1);
}
__global__ void scan1_kernel() {
    __shared__ int sm[SB];
    int i = blockIdx.x * SB + threadIdx.x;
    sm[threadIdx.x] = (i < N_NODES) ? g_deg[i] : 0;
    __syncthreads();
    for (int off = SB / 2; off > 0; off >>= 1) {
        if (threadIdx.x < off) sm[threadIdx.x] += sm[threadIdx.x + off];
        __syncthreads();
    }
    if (threadIdx.x == 0) g_bsum[blockIdx.x] = sm[0];
}
__global__ void scan2_kernel() {
    __shared__ int sm[256];
    int t = threadIdx.x;
    int v = (t < NSB) ? g_bsum[t] : 0;
    sm[t] = v;
    __syncthreads();
    for (int off = 1; off < 256; off <<= 1) {
        int u = (t >= off) ? sm[t - off] : 0;
        __syncthreads();
        sm[t] += u;
        __syncthreads();
    }
    if (t < NSB) g_bsum[t] = sm[t] - v;
}
__global__ void scan3_kernel() {
    __shared__ int sm[SB];
    int t = threadIdx.x;
    int i = blockIdx.x * SB + t;
    int d = (i < N_NODES) ? g_deg[i] : 0;
    sm[t] = d;
    __syncthreads();
    for (int off = 1; off < SB; off <<= 1) {
        int u = (t >= off) ? sm[t - off] : 0;
        __syncthreads();
        sm[t] += u;
        __syncthreads();
    }
    int excl = g_bsum[blockIdx.x] + sm[t] - d;
    if (i < N_NODES) { g_rowptr[i] = excl; g_cursor[i] = excl; }
    if (blockIdx.x == 0 && t == 0) g_rowptr[N_NODES] = E_TOT;
}
__global__ void scatter_kernel() {
    int e = blockIdx.x * blockDim.x + threadIdx.x;
    if (e >= E_TOT) return;
    int d = g_dst[e];
    int pos = atomicAdd(&g_cursor[d], 1);
    g_csr_src[pos] = g_src[e];
}

// ---------------- fp32 -> bf16 hi/lo split (layer-0 input only) --------------
__global__ void split_kernel(const float* __restrict__ src, int total4) {
    int i = blockIdx.x * blockDim.x + threadIdx.x;
    if (i >= total4) return;
    float4 v = ((const float4*)src)[i];
    __nv_bfloat16 h0 = __float2bfloat16(v.x), h1 = __float2bfloat16(v.y);
    __nv_bfloat16 h2 = __float2bfloat16(v.z), h3 = __float2bfloat16(v.w);
    __nv_bfloat16 l0 = __float2bfloat16(v.x - __bfloat162float(h0));
    __nv_bfloat16 l1 = __float2bfloat16(v.y - __bfloat162float(h1));
    __nv_bfloat16 l2 = __float2bfloat16(v.z - __bfloat162float(h2));
    __nv_bfloat16 l3 = __float2bfloat16(v.w - __bfloat162float(h3));
    ((__nv_bfloat162*)g_Ahi)[2 * i + 0] = __nv_bfloat162(h0, h1);
    ((__nv_bfloat162*)g_Ahi)[2 * i + 1] = __nv_bfloat162(h2, h3);
    ((__nv_bfloat162*)g_Alo)[2 * i + 0] = __nv_bfloat162(l0, l1);
    ((__nv_bfloat162*)g_Alo)[2 * i + 1] = __nv_bfloat162(l2, l3);
}
// coalesced transpose+split: W[K,N] -> Whi/Wlo [N,K] via 32x32 smem tiles
__global__ void wsplit_kernel(const float* __restrict__ W, int K, int N) {
    __shared__ float t[32][33];
    int nb = blockIdx.x * 32, kb = blockIdx.y * 32;
    int tx = threadIdx.x, ty = threadIdx.y;   // (32, 8)
#pragma unroll
    for (int j = 0; j < 4; j++)
        t[ty + j * 8][tx] = W[(size_t)(kb + ty + j * 8) * N + nb + tx];
    __syncthreads();
#pragma unroll
    for (int j = 0; j < 4; j++) {
        int n = nb + ty + j * 8, k = kb + tx;
        float v = t[tx][ty + j * 8];
        __nv_bfloat16 h = __float2bfloat16(v);
        g_Whi[(size_t)n * K + k] = h;
        g_Wlo[(size_t)n * K + k] = __float2bfloat16(v - __bfloat162float(h));
    }
}

// ---------------- HMMA bf16 GEMM (3-pass split, cp.async, fused alpha) -------
template <int BN>
__global__ __launch_bounds__(256, 2) void mma_gemm_kernel(
        float* __restrict__ D, const float* __restrict__ a_s,
        const float* __restrict__ a_d, int M, int N, int K, int H, int C) {
    extern __shared__ __align__(1024) char smem[];
    char* Abuf[2] = { smem, smem + 16384 };
    char* Bbuf[2] = { smem + 32768, smem + 32768 + BN * 128 };

    const int tid = threadIdx.x;
    const int wid = tid >> 5, lane = tid & 31;
    const int rowBase = blockIdx.y * 128;
    const int colBase = blockIdx.x * BN;
    const int wr = wid >> 2, wc = wid & 3;      // warp grid 2 x 4
    constexpr int WN = BN / 4;
    constexpr int NT = WN / 8;
    const int warpRow = wr * 64, warpCol = wc * WN;

    float acc[4][NT][4];
#pragma unroll
    for (int i = 0; i < 4; i++)
#pragma unroll
        for (int j = 0; j < NT; j++)
#pragma unroll
            for (int q = 0; q < 4; q++) acc[i][j][q] = 0.f;

    const int kch = K / 64;
    const int NCH = 3 * kch;

    auto load_async = [&](int i, char* sA, char* sB) {
        int pass = i / kch, kc = i - pass * kch;
        const __nv_bfloat16* Asrc = (pass == 2) ? g_Alo : g_Ahi;
        const __nv_bfloat16* Bsrc = (pass == 1) ? g_Wlo : g_Whi;
        uint32_t sAu = smem_u32(sA), sBu = smem_u32(sB);
#pragma unroll
        for (int j = 0; j < 4; j++) {
            int q = tid + j * 256;
            int r = q >> 3, c16 = q & 7;
            const void* src = Asrc + (size_t)(rowBase + r) * K + kc * 64 + c16 * 8;
            int bytes = (rowBase + r < M) ? 16 : 0;
            CP_ASYNC16(sAu + sw128(r * 128 + c16 * 16), src, bytes);
        }
#pragma unroll
        for (int j = 0; j < BN / 32; j++) {
            int q = tid + j * 256;
            int r = q >> 3, c16 = q & 7;
            const void* src = Bsrc + (size_t)(colBase + r) * K + kc * 64 + c16 * 8;
            CP_ASYNC16(sBu + sw128(r * 128 + c16 * 16), src, 16);
        }
        CP_COMMIT();
    };

    load_async(0, Abuf[0], Bbuf[0]);
    CP_WAIT0();
    __syncthreads();

    const int g = lane >> 3;
    const int l7 = lane & 7;

    for (int i = 0; i < NCH; i++) {
        int cur = i & 1;
        if (i + 1 < NCH) load_async(i + 1, Abuf[cur ^ 1], Bbuf[cur ^ 1]);

        uint32_t aBase = smem_u32(Abuf[cur]);
        uint32_t bBase = smem_u32(Bbuf[cur]);
#pragma unroll
        for (int kk = 0; kk < 4; kk++) {
            uint32_t af[4][4];
#pragma unroll
            for (int mt = 0; mt < 4; mt++) {
                int row = warpRow + mt * 16 + l7 + ((g & 1) ? 8 : 0);
                int kb = (kk * 16 + ((g >= 2) ? 8 : 0)) * 2;
                uint32_t addr = aBase + sw128((uint32_t)(row * 128 + kb));
                LDSM_X4(af[mt][0], af[mt][1], af[mt][2], af[mt][3], addr);
            }
            uint32_t bf[NT][2];
#pragma unroll
            for (int np = 0; np < NT / 2; np++) {
                int row = warpCol + np * 16 + l7 + ((g >= 2) ? 8 : 0);
                int kb = (kk * 16 + ((g & 1) ? 8 : 0)) * 2;
                uint32_t addr = bBase + sw128((uint32_t)(row * 128 + kb));
                uint32_t r0, r1, r2, r3;
                LDSM_X4(r0, r1, r2, r3, addr);
                bf[np * 2][0] = r0;  bf[np * 2][1] = r1;
                bf[np * 2 + 1][0] = r2; bf[np * 2 + 1][1] = r3;
            }
#pragma unroll
            for (int mt = 0; mt < 4; mt++)
#pragma unroll
                for (int nt = 0; nt < NT; nt++)
                    mma16816(acc[mt][nt], af[mt], bf[nt]);
        }
        CP_WAIT0();
        __syncthreads();
    }

    // ---------------- epilogue: store D + fused alpha dots -------------------
    const int qr = lane >> 2, qc = lane & 3;
#pragma unroll
    for (int mt = 0; mt < 4; mt++) {
        int r0 = rowBase + warpRow + mt * 16 + qr;
#pragma unroll
        for (int nt = 0; nt < NT; nt++) {
            int col = colBase + warpCol + nt * 8 + qc * 2;
            if (r0 < M)
                *(float2*)&D[(size_t)r0 * N + col] = make_float2(acc[mt][nt][0], acc[mt][nt][1]);
            if (r0 + 8 < M)
                *(float2*)&D[(size_t)(r0 + 8) * N + col] = make_float2(acc[mt][nt][2], acc[mt][nt][3]);
        }
    }

    float* sAs   = (float*)smem;
    float* sAd   = sAs + BN;
    float* sRedS = sAd + BN;
    float* sRedD = sRedS + 4 * 128;
    if (tid < BN) {
        sAs[tid] = a_s[colBase + tid];
        sAd[tid] = a_d[colBase + tid];
    }
    __syncthreads();

#pragma unroll
    for (int mt = 0; mt < 4; mt++) {
        float s0 = 0.f, s1 = 0.f, d0 = 0.f, d1 = 0.f;
#pragma unroll
        for (int nt = 0; nt < NT; nt++) {
#pragma unroll
            for (int q = 0; q < 2; q++) {
                int cl = warpCol + nt * 8 + qc * 2 + q;
                float as = sAs[cl], ad = sAd[cl];
                s0 += acc[mt][nt][q] * as;     d0 += acc[mt][nt][q] * ad;
                s1 += acc[mt][nt][2 + q] * as; d1 += acc[mt][nt][2 + q] * ad;
            }
        }
#pragma unroll
        for (int o = 2; o; o >>= 1) {
            s0 += __shfl_down_sync(0xffffffffu, s0, o, 4);
            s1 += __shfl_down_sync(0xffffffffu, s1, o, 4);
            d0 += __shfl_down_sync(0xffffffffu, d0, o, 4);
            d1 += __shfl_down_sync(0xffffffffu, d1, o, 4);
        }
        if (qc == 0) {
            int rl = warpRow + mt * 16 + qr;
            sRedS[wc * 128 + rl] = s0;  sRedS[wc * 128 + rl + 8] = s1;
            sRedD[wc * 128 + rl] = d0;  sRedD[wc * 128 + rl + 8] = d1;
        }
    }
    __syncthreads();

    if (tid < 128) {
        int grow = rowBase + tid;
        if (grow < M) {
            int hpb = (BN > C) ? (BN / C) : 1;
            int wph = 4 / hpb;
            int headBase = colBase / C;
            for (int hh = 0; hh < hpb; hh++) {
                float as = 0.f, ad = 0.f;
                for (int w = 0; w < wph; w++) {
                    as += sRedS[(hh * wph + w) * 128 + tid];
                    ad += sRedD[(hh * wph + w) * 128 + tid];
                }
                g_asrc[grow * H + headBase + hh] = as;
                g_adst[grow * H + headBase + hh] = ad;
            }
        }
    }
}

// ---------------- warp-per-node softmax stats (max + 1/denom) ----------------
template <int H>
__global__ void attn_stats_kernel() {
    int w = (blockIdx.x * blockDim.x + threadIdx.x) >> 5;
    int lane = threadIdx.x & 31;
    if (w >= N_NODES) return;
    int start = g_rowptr[w], end = g_rowptr[w + 1];

    float adst[H];
#pragma unroll
    for (int h = 0; h < H; h++) adst[h] = g_adst[w * H + h];

    float lmax[H];
#pragma unroll
    for (int h = 0; h < H; h++) lmax[h] = -INFINITY;
    for (int i = start + lane; i < end; i += 32) {
        int s = g_csr_src[i];
#pragma unroll
        for (int h = 0; h < H; h++) {
            float v = g_asrc[s * H + h] + adst[h];
            v = (v > 0.f) ? v : 0.2f * v;
            lmax[h] = fmaxf(lmax[h], v);
        }
    }
#pragma unroll
    for (int h = 0; h < H; h++)
#pragma unroll
        for (int o = 16; o; o >>= 1)
            lmax[h] = fmaxf(lmax[h], __shfl_xor_sync(0xffffffffu, lmax[h], o));

    float lsum[H];
#pragma unroll
    for (int h = 0; h < H; h++) lsum[h] = 0.f;
    for (int i = start + lane; i < end; i += 32) {
        int s = g_csr_src[i];
#pragma unroll
        for (int h = 0; h < H; h++) {
            float v = g_asrc[s * H + h] + adst[h];
            v = (v > 0.f) ? v : 0.2f * v;
            lsum[h] += __expf(v - lmax[h]);
        }
    }
#pragma unroll
    for (int h = 0; h < H; h++)
#pragma unroll
        for (int o = 16; o; o >>= 1)
            lsum[h] += __shfl_xor_sync(0xffffffffu, lsum[h], o);

    if (lane == 0) {
#pragma unroll
        for (int h = 0; h < H; h++) {
            g_emax[w * H + h] = lmax[h];
            g_invd[w * H + h] = 1.f / lsum[h];
        }
    }
}

// ---------------- gather-aggregate w/ inline alpha + bias + relu -------------
template <int H, int C, bool SPLIT>
__global__ void agg_kernel(const float* __restrict__ bias, float* __restrict__ out) {
    constexpr int HC = H * C;
    constexpr int NV = HC / 4;
    int d = blockIdx.x;
    int tid = threadIdx.x;
    if (tid >= NV) return;
    int c4 = tid * 4;
    int head = c4 / C;
    int start = g_rowptr[d], end = g_rowptr[d + 1];

    float adst = g_adst[d * H + head];
    float bm   = g_emax[d * H + head];
    float inv  = g_invd[d * H + head];

    float4 acc = make_float4(0.f, 0.f, 0.f, 0.f);
    for (int pos = start; pos < end; pos++) {
        int s = g_csr_src[pos];
        float v = g_asrc[s * H + head] + adst;
        v = (v > 0.f) ? v : 0.2f * v;
        float al = __expf(v - bm) * inv;
        float4 hv = *(const float4*)&g_h[(size_t)s * HC + c4];
        acc.x += hv.x * al; acc.y += hv.y * al;
        acc.z += hv.z * al; acc.w += hv.w * al;
    }
    float4 bv = *(const float4*)&bias[c4];
    acc.x = fmaxf(acc.x + bv.x, 0.f);
    acc.y = fmaxf(acc.y + bv.y, 0.f);
    acc.z = fmaxf(acc.z + bv.z, 0.f);
    acc.w = fmaxf(acc.w + bv.w, 0.f);
    if (SPLIT) {
        size_t base = (size_t)d * HC + c4;
        __nv_bfloat16 h0 = __float2bfloat16(acc.x), h1 = __float2bfloat16(acc.y);
        __nv_bfloat16 h2 = __float2bfloat16(acc.z), h3 = __float2bfloat16(acc.w);
        __nv_bfloat16 l0 = __float2bfloat16(acc.x - __bfloat162float(h0));
        __nv_bfloat16 l1 = __float2bfloat16(acc.y - __bfloat162float(h1));
        __nv_bfloat16 l2 = __float2bfloat16(acc.z - __bfloat162float(h2));
        __nv_bfloat16 l3 = __float2bfloat16(acc.w - __bfloat162float(h3));
        ((__nv_bfloat162*)(g_Ahi + base))[0] = __nv_bfloat162(h0, h1);
        ((__nv_bfloat162*)(g_Ahi + base))[1] = __nv_bfloat162(h2, h3);
        ((__nv_bfloat162*)(g_Alo + base))[0] = __nv_bfloat162(l0, l1);
        ((__nv_bfloat162*)(g_Alo + base))[1] = __nv_bfloat162(l2, l3);
    } else {
        *(float4*)&out[(size_t)d * HC + c4] = acc;
    }
}

// ---------------- driver ------------------------------------------------------
extern "C" void kernel_launch(void* const* d_in, const int* in_sizes, int n_in,
                              void* d_out, int out_size) {
    const float* x  = (const float*)d_in[0];
    const void*  ei = d_in[1];
    float* out = (float*)d_out;

    void* p;
    cudaGetSymbolAddress(&p, g_h);
    float* h_ptr = (float*)p;

    static bool attr_done = false;
    if (!attr_done) {
        cudaFuncSetAttribute(mma_gemm_kernel<128>, cudaFuncAttributeMaxDynamicSharedMemorySize,
                             2 * 16384 + 2 * 128 * 128);
        cudaFuncSetAttribute(mma_gemm_kernel<64>, cudaFuncAttributeMaxDynamicSharedMemorySize,
                             2 * 16384 + 2 * 64 * 128);
        attr_done = true;
    }

    struct Cfg { const float *W, *as, *ad, *b; int Fin, H, C; };
    Cfg cfg[4] = {
        { (const float*)d_in[2],  (const float*)d_in[3],  (const float*)d_in[4],  (const float*)d_in[5],  256, 4, 128 },
        { (const float*)d_in[6],  (const float*)d_in[7],  (const float*)d_in[8],  (const float*)d_in[9],  512, 4, 128 },
        { (const float*)d_in[10], (const float*)d_in[11], (const float*)d_in[12], (const float*)d_in[13], 512, 4,  64 },
        { (const float*)d_in[14], (const float*)d_in[15], (const float*)d_in[16], (const float*)d_in[17], 256, 1,  64 },
    };

    detect_dtype_kernel<<<1, 1>>>((const int*)ei);
    zero_deg_kernel<<<(N_NODES + TPB - 1) / TPB, TPB>>>();
    build_edges_kernel<<<(E_TOT + TPB - 1) / TPB, TPB>>>(ei);
    scan1_kernel<<<NSB, SB>>>();
    scan2_kernel<<<1, 256>>>();
    scan3_kernel<<<NSB, SB>>>();
    scatter_kernel<<<(E_TOT + TPB - 1) / TPB, TPB>>>();

    {
        int total4 = N_NODES * 256 / 4;
        split_kernel<<<(total4 + TPB - 1) / TPB, TPB>>>(x, total4);
    }

    const int MT = (N_NODES + 127) / 128;
    const int AW = (N_NODES * 32 + TPB - 1) / TPB;   // warp-per-node grid

    for (int L = 0; L < 4; L++) {
        const Cfg& c = cfg[L];
        int HC = c.H * c.C;

        {
            dim3 wgrid(HC / 32, c.Fin / 32);
            wsplit_kernel<<<wgrid, dim3(32, 8)>>>(c.W, c.Fin, HC);
        }

        if (HC >= 128) {
            dim3 grid(HC / 128, MT);
            mma_gemm_kernel<128><<<grid, 256, 2 * 16384 + 2 * 128 * 128>>>(
                h_ptr, c.as, c.ad, N_NODES, HC, c.Fin, c.H, c.C);
        } else {
            dim3 grid(HC / 64, MT);
            mma_gemm_kernel<64><<<grid, 256, 2 * 16384 + 2 * 64 * 128>>>(
                h_ptr, c.as, c.ad, N_NODES, HC, c.Fin, c.H, c.C);
        }

        switch (L) {
            case 0:
                attn_stats_kernel<4><<<AW, TPB>>>();
                agg_kernel<4, 128, true><<<N_NODES, 128>>>(c.b, nullptr);
                break;
            case 1:
                attn_stats_kernel<4><<<AW, TPB>>>();
                agg_kernel<4, 128, true><<<N_NODES, 128>>>(c.b, nullptr);
                break;
            case 2:
                attn_stats_kernel<4><<<AW, TPB>>>();
                agg_kernel<4, 64, true><<<N_NODES, 64>>>(c.b, nullptr);
                break;
            case 3:
                attn_stats_kernel<1><<<AW, TPB>>>();
                agg_kernel<1, 64, false><<<N_NODES, 32>>>(c.b, out);
                break;
        }
    }
}